// round 7
// baseline (speedup 1.0000x reference)
#include <cuda_runtime.h>
#include <cstdint>

#define BATCH  4096
#define NIN    784
#define H1     100
#define H1P    128
#define H2     10
#define NSTEP  100
#define TBEGIN 20
#define KT     28                 // k-chunk per smem stage
#define NCHUNK 28                 // 784 / 28
#define RT     16                 // batch rows per layer-1 CTA
#define L1CTAS 256                // 4096 / 16
#define L2CTAS 16                 // 4096 / 256
#define WS_ELE (KT * H1P)         // 3584 W floats per chunk
#define XI_ELE (KT * RT)          // 448 dup'd 8B entries per chunk
#define DYN_SMEM (2 * WS_ELE * 4 + 2 * XI_ELE * 8)   // 28672 + 7168 = 35840 B

// ---------------- device globals ----------------
__device__ float g_W1p[NIN * H1P];           // padded W1 [k][128 h]
__device__ float g_xT[NIN * BATCH];          // transposed input [k][row]
__device__ float g_inner1[BATCH * H1P];
__device__ float g_outer1[2][BATCH * H1P];
__device__ float g_inner2[BATCH * H2];
__device__ float g_acc[BATCH * H2];

// ---------------- packed fp32x2 FMA ----------------
__device__ __forceinline__ void ffma2(unsigned long long &a,
                                      unsigned long long xv,
                                      unsigned long long wv) {
    asm("fma.rn.f32x2 %0, %1, %2, %0;" : "+l"(a) : "l"(xv), "l"(wv));
}
__device__ __forceinline__ void unpack2(unsigned long long a, float &lo, float &hi) {
    asm("mov.b64 {%0,%1}, %2;" : "=f"(lo), "=f"(hi) : "l"(a));
}
__device__ __forceinline__ unsigned long long dup2(float v) {
    unsigned long long d;
    asm("mov.b64 %0, {%1,%1};" : "=l"(d) : "f"(v));
    return d;
}

// ---------------- threefry2x32 (JAX-exact) ----------------
__device__ __forceinline__ void tf2x32(unsigned k0, unsigned k1,
                                       unsigned x0, unsigned x1,
                                       unsigned &o0, unsigned &o1) {
    unsigned ks2 = k0 ^ k1 ^ 0x1BD11BDAu;
    x0 += k0; x1 += k1;
#define TFR(r) { x0 += x1; x1 = __funnelshift_l(x1, x1, (r)); x1 ^= x0; }
    TFR(13) TFR(15) TFR(26) TFR(6);  x0 += k1;  x1 += ks2 + 1u;
    TFR(17) TFR(29) TFR(16) TFR(24); x0 += ks2; x1 += k0 + 2u;
    TFR(13) TFR(15) TFR(26) TFR(6);  x0 += k0;  x1 += k1 + 3u;
    TFR(17) TFR(29) TFR(16) TFR(24); x0 += k1;  x1 += ks2 + 4u;
    TFR(13) TFR(15) TFR(26) TFR(6);  x0 += ks2; x1 += k0 + 5u;
#undef TFR
    o0 = x0; o1 = x1;
}
__device__ __forceinline__ float tf_uniform(unsigned k0, unsigned k1, unsigned idx) {
    unsigned o0, o1;
    tf2x32(k0, k1, 0u, idx, o0, o1);
    unsigned bits = o0 ^ o1;
    return __uint_as_float((bits >> 9) | 0x3f800000u) - 1.0f;
}

// ---------------- init: states, padded W1, transposed x ----------------
__global__ void init_k(const float* __restrict__ W1, const float* __restrict__ x) {
    int stride = gridDim.x * blockDim.x;
    int tid = blockIdx.x * blockDim.x + threadIdx.x;
    for (int i = tid; i < BATCH * H1P; i += stride) {
        g_inner1[i] = 0.0f; g_outer1[0][i] = 0.0f; g_outer1[1][i] = 0.0f;
    }
    for (int i = tid; i < BATCH * H2; i += stride) {
        g_inner2[i] = 0.0f; g_acc[i] = 0.0f;
    }
    for (int i = tid; i < NIN * H1P; i += stride) {
        int k = i >> 7, h = i & 127;
        g_W1p[i] = (h < H1) ? W1[k * H1 + h] : 0.0f;
    }
    for (int i = tid; i < NIN * BATCH; i += stride) {
        int k = i >> 12, r = i & 4095;          // i = k*4096 + r
        g_xT[i] = x[r * NIN + k];
    }
}

// ---------------- per-step kernel: warp-specialized, 2 CTAs/SM ----------------
__global__ void __launch_bounds__(256, 2)
step_k(const float* __restrict__ b1,
       const float* __restrict__ W2,
       const float* __restrict__ b2,
       unsigned key0, unsigned key1, int t)
{
    extern __shared__ float dyn[];
    float* sh_ws = dyn;                                        // [2][WS_ELE]
    unsigned long long* sh_xi =
        (unsigned long long*)(dyn + 2 * WS_ELE);               // [2][XI_ELE]

    const int tid = threadIdx.x;

    if (blockIdx.x < L1CTAS) {
        const int r0 = blockIdx.x * RT;

        if (tid < 128) {
            // ===== CONSUMER: 4 warps, each 4 rows x 128 h =====
            const int lane  = tid & 31;
            const int wrow0 = (tid >> 5) * 4;          // warp w -> rows w*4..w*4+3
            float* __restrict__ outw = g_outer1[t & 1];

            // acc2[row 0..3][hpair 0..1]: h = 4*lane + 2*hp (+1)
            unsigned long long acc2[4][2];
            #pragma unroll
            for (int a = 0; a < 4; ++a) { acc2[a][0] = 0ull; acc2[a][1] = 0ull; }

            for (int c = 0; c < NCHUNK; ++c) {
                __syncthreads();                        // buf[c&1] ready
                const float* ws = sh_ws + (c & 1) * WS_ELE;
                const unsigned long long* xs = sh_xi + (c & 1) * XI_ELE;

                #pragma unroll 7
                for (int k = 0; k < KT; ++k) {
                    const ulonglong2* ap = (const ulonglong2*)(xs + k * RT + wrow0);
                    ulonglong2 aA = ap[0];   // rows 0,1 (dup'd)
                    ulonglong2 aB = ap[1];   // rows 2,3
                    ulonglong2 bv = *(const ulonglong2*)&ws[k * H1P + lane * 4];
                    ffma2(acc2[0][0], aA.x, bv.x); ffma2(acc2[0][1], aA.x, bv.y);
                    ffma2(acc2[1][0], aA.y, bv.x); ffma2(acc2[1][1], aA.y, bv.y);
                    ffma2(acc2[2][0], aB.x, bv.x); ffma2(acc2[2][1], aB.x, bv.y);
                    ffma2(acc2[3][0], aB.y, bv.x); ffma2(acc2[3][1], aB.y, bv.y);
                }
            }

            // ---- LIF epilogue: 4 rows x 4 h per lane ----
            float4 bias = make_float4(0.f, 0.f, 0.f, 0.f);
            if (lane < 25) bias = *(const float4*)&b1[lane * 4];
            #pragma unroll
            for (int rr = 0; rr < 4; ++rr) {
                int r = r0 + wrow0 + rr;
                float e0, e1, e2, e3;
                unpack2(acc2[rr][0], e0, e1);
                unpack2(acc2[rr][1], e2, e3);
                e0 += bias.x; e1 += bias.y; e2 += bias.z; e3 += bias.w;
                float4 piv = *(const float4*)&g_inner1[r * H1P + lane * 4];
                float n0 = fmaf(piv.x, 0.9f, e0);
                float n1 = fmaf(piv.y, 0.9f, e1);
                float n2 = fmaf(piv.z, 0.9f, e2);
                float n3 = fmaf(piv.w, 0.9f, e3);
                float o0 = fmaxf(n0 - 1.0f, 0.0f);
                float o1 = fmaxf(n1 - 1.0f, 0.0f);
                float o2 = fmaxf(n2 - 1.0f, 0.0f);
                float o3 = fmaxf(n3 - 1.0f, 0.0f);
                *(float4*)&outw[r * H1P + lane * 4] = make_float4(o0, o1, o2, o3);
                if (o0 > 0.0f) n0 = -0.5f * n0;
                if (o1 > 0.0f) n1 = -0.5f * n1;
                if (o2 > 0.0f) n2 = -0.5f * n2;
                if (o3 > 0.0f) n3 = -0.5f * n3;
                *(float4*)&g_inner1[r * H1P + lane * 4] = make_float4(n0, n1, n2, n3);
            }
        } else {
            // ===== PRODUCER: 4 warps, RNG + staging =====
            const int ptid = tid - 128;                 // 0..127

            float4 wreg[7];
            float  xreg[4];

            // prologue: load chunk 0, stage into buf 0
            {
                const float4* wsrc = (const float4*)g_W1p;
                #pragma unroll
                for (int i = 0; i < 7; ++i) wreg[i] = wsrc[ptid + i * 128];
                #pragma unroll
                for (int i = 0; i < 4; ++i) {
                    int idx = i * 128 + ptid;
                    xreg[i] = (idx < XI_ELE) ? g_xT[(idx >> 4) * BATCH + r0 + (idx & 15)] : 0.0f;
                }
                float4* wdst = (float4*)sh_ws;
                #pragma unroll
                for (int i = 0; i < 7; ++i) wdst[ptid + i * 128] = wreg[i];
                #pragma unroll
                for (int i = 0; i < 4; ++i) {
                    int idx = i * 128 + ptid;
                    if (idx < XI_ELE) {
                        int k = idx >> 4, row = idx & 15;
                        unsigned j = (unsigned)((r0 + row) * NIN + k);
                        sh_xi[idx] = dup2(tf_uniform(key0, key1, j) * xreg[i]);
                    }
                }
            }

            for (int c = 0; c < NCHUNK; ++c) {
                __syncthreads();                        // consumers own buf[c&1]
                if (c + 1 < NCHUNK) {
                    const int buf = (c + 1) & 1;
                    const int kc  = (c + 1) * KT;
                    const float4* wsrc = (const float4*)(g_W1p + (c + 1) * WS_ELE);
                    #pragma unroll
                    for (int i = 0; i < 7; ++i) wreg[i] = wsrc[ptid + i * 128];
                    #pragma unroll
                    for (int i = 0; i < 4; ++i) {
                        int idx = i * 128 + ptid;
                        xreg[i] = (idx < XI_ELE) ? g_xT[(kc + (idx >> 4)) * BATCH + r0 + (idx & 15)] : 0.0f;
                    }
                    float4* wdst = (float4*)(sh_ws + buf * WS_ELE);
                    #pragma unroll
                    for (int i = 0; i < 7; ++i) wdst[ptid + i * 128] = wreg[i];
                    unsigned long long* xdst = sh_xi + buf * XI_ELE;
                    #pragma unroll
                    for (int i = 0; i < 4; ++i) {
                        int idx = i * 128 + ptid;
                        if (idx < XI_ELE) {
                            int k = idx >> 4, row = idx & 15;
                            unsigned j = (unsigned)((r0 + row) * NIN + kc + k);
                            xdst[idx] = dup2(tf_uniform(key0, key1, j) * xreg[i]);
                        }
                    }
                }
            }
        }
    } else {
        // ================= LAYER 2 =================
        float* sh_w2 = dyn;
        float* sh_b2 = dyn + H1 * H2;
        for (int i = tid; i < H1 * H2; i += 256) sh_w2[i] = W2[i];
        if (tid < H2) sh_b2[tid] = b2[tid];
        __syncthreads();

        int r = (blockIdx.x - L1CTAS) * 256 + tid;
        const float* __restrict__ po = g_outer1[(t & 1) ^ 1] + r * H1P;  // delayed

        float s[H2];
        #pragma unroll
        for (int h2 = 0; h2 < H2; ++h2) s[h2] = sh_b2[h2];

        for (int k = 0; k < H1; k += 4) {
            float4 p = *(const float4*)&po[k];
            #pragma unroll
            for (int h2 = 0; h2 < H2; ++h2) {
                float a = s[h2];
                a = fmaf(p.x, sh_w2[(k + 0) * H2 + h2], a);
                a = fmaf(p.y, sh_w2[(k + 1) * H2 + h2], a);
                a = fmaf(p.z, sh_w2[(k + 2) * H2 + h2], a);
                a = fmaf(p.w, sh_w2[(k + 3) * H2 + h2], a);
                s[h2] = a;
            }
        }

        #pragma unroll
        for (int h2 = 0; h2 < H2; ++h2) {
            float pi = g_inner2[r * H2 + h2];
            if (t >= TBEGIN) g_acc[r * H2 + h2] += pi;   // delayed state
            float ni = fmaf(pi, 0.9f, s[h2]);
            float d  = ni - 1.0f;
            if (d > 0.0f) ni = ni - 1.5f * ni;
            g_inner2[r * H2 + h2] = ni;
        }
    }
}

// ---------------- finalize: log_softmax ----------------
__global__ void final_k(float* __restrict__ out) {
    int r = blockIdx.x * blockDim.x + threadIdx.x;
    if (r >= BATCH) return;
    float v[H2];
    float m = -3.402823466e38f;
    #pragma unroll
    for (int c = 0; c < H2; ++c) { v[c] = g_acc[r * H2 + c]; m = fmaxf(m, v[c]); }
    float sum = 0.0f;
    #pragma unroll
    for (int c = 0; c < H2; ++c) sum += expf(v[c] - m);
    float l = logf(sum);
    #pragma unroll
    for (int c = 0; c < H2; ++c) out[r * H2 + c] = v[c] - m - l;
}

// ---------------- host threefry ----------------
static inline unsigned h_rotl(unsigned v, int r) { return (v << r) | (v >> (32 - r)); }
static void host_tf2x32(unsigned k0, unsigned k1, unsigned x0, unsigned x1,
                        unsigned* o0, unsigned* o1) {
    unsigned ks2 = k0 ^ k1 ^ 0x1BD11BDAu;
    x0 += k0; x1 += k1;
#define HTFR(r) { x0 += x1; x1 = h_rotl(x1, (r)); x1 ^= x0; }
    HTFR(13) HTFR(15) HTFR(26) HTFR(6);  x0 += k1;  x1 += ks2 + 1u;
    HTFR(17) HTFR(29) HTFR(16) HTFR(24); x0 += ks2; x1 += k0 + 2u;
    HTFR(13) HTFR(15) HTFR(26) HTFR(6);  x0 += k0;  x1 += k1 + 3u;
    HTFR(17) HTFR(29) HTFR(16) HTFR(24); x0 += k1;  x1 += ks2 + 4u;
    HTFR(13) HTFR(15) HTFR(26) HTFR(6);  x0 += ks2; x1 += k0 + 5u;
#undef HTFR
    *o0 = x0; *o1 = x1;
}

extern "C" void kernel_launch(void* const* d_in, const int* in_sizes, int n_in,
                              void* d_out, int out_size) {
    const float* x  = (const float*)d_in[0];
    const float* W1 = (const float*)d_in[1];
    const float* b1 = (const float*)d_in[2];
    const float* W2 = (const float*)d_in[3];
    const float* b2 = (const float*)d_in[4];
    float* out = (float*)d_out;

    cudaFuncSetAttribute(step_k, cudaFuncAttributeMaxDynamicSharedMemorySize, DYN_SMEM);

    init_k<<<1024, 256>>>(W1, x);

    for (int t = 0; t < NSTEP; ++t) {
        unsigned k0, k1;
        host_tf2x32(0u, 42u, 0u, (unsigned)t, &k0, &k1);
        step_k<<<L1CTAS + L2CTAS, 256, DYN_SMEM>>>(b1, W2, b2, k0, k1, t);
    }

    final_k<<<16, 256>>>(out);
    (void)in_sizes; (void)n_in; (void)out_size;
}

// round 8
// speedup vs baseline: 1.7033x; 1.7033x over previous
#include <cuda_runtime.h>
#include <cstdint>

#define BATCH  4096
#define NIN    784
#define H1     100
#define H1P    128
#define H2     10
#define NSTEP  100
#define TBEGIN 20
#define KT     56
#define NCHUNK 14
#define RT     32
#define NCTAS  128                 // 4096 / 32
#define WS_ELE (KT * H1P)          // 7168
#define XI_ELE (KT * RT)           // 1792

// smem layout (float offsets)
#define OFF_WS    0                // [2][7168]
#define OFF_XI    14336            // [2][1792] ull  (7168 floats)
#define OFF_OUT   21504            // [2][4096]
#define OFF_W2T   29696            // [1012]
#define OFF_B2    30708            // [12]
#define OFF_KEYS  30720            // [100] uint2 (200 floats)
#define OFF_ACC   30920            // [320]
#define DYN_SMEM  (31240 * 4)      // 124960 B

// ---------------- device globals ----------------
__device__ float g_W1p[NIN * H1P];           // padded W1 [k][128]
__device__ float g_xT[NIN * BATCH];          // transposed input [k][row]
__device__ uint2 g_keys[NSTEP];

// ---------------- packed fp32x2 ----------------
__device__ __forceinline__ void ffma2(unsigned long long &a,
                                      unsigned long long xv,
                                      unsigned long long wv) {
    asm("fma.rn.f32x2 %0, %1, %2, %0;" : "+l"(a) : "l"(xv), "l"(wv));
}
__device__ __forceinline__ void unpack2(unsigned long long a, float &lo, float &hi) {
    asm("mov.b64 {%0,%1}, %2;" : "=f"(lo), "=f"(hi) : "l"(a));
}
__device__ __forceinline__ unsigned long long dup2(float v) {
    unsigned long long d;
    asm("mov.b64 %0, {%1,%1};" : "=l"(d) : "f"(v));
    return d;
}

// ---------------- threefry2x32 (JAX-exact) ----------------
__device__ __forceinline__ void tf2x32(unsigned k0, unsigned k1,
                                       unsigned x0, unsigned x1,
                                       unsigned &o0, unsigned &o1) {
    unsigned ks2 = k0 ^ k1 ^ 0x1BD11BDAu;
    x0 += k0; x1 += k1;
#define TFR(r) { x0 += x1; x1 = __funnelshift_l(x1, x1, (r)); x1 ^= x0; }
    TFR(13) TFR(15) TFR(26) TFR(6);  x0 += k1;  x1 += ks2 + 1u;
    TFR(17) TFR(29) TFR(16) TFR(24); x0 += ks2; x1 += k0 + 2u;
    TFR(13) TFR(15) TFR(26) TFR(6);  x0 += k0;  x1 += k1 + 3u;
    TFR(17) TFR(29) TFR(16) TFR(24); x0 += k1;  x1 += ks2 + 4u;
    TFR(13) TFR(15) TFR(26) TFR(6);  x0 += ks2; x1 += k0 + 5u;
#undef TFR
    o0 = x0; o1 = x1;
}
__device__ __forceinline__ float tf_uniform(unsigned k0, unsigned k1, unsigned idx) {
    unsigned o0, o1;
    tf2x32(k0, k1, 0u, idx, o0, o1);
    unsigned bits = o0 ^ o1;
    return __uint_as_float((bits >> 9) | 0x3f800000u) - 1.0f;
}

// ---------------- init: padded W1, transposed x, per-step keys ----------------
__global__ void init_k(const float* __restrict__ W1, const float* __restrict__ x) {
    int stride = gridDim.x * blockDim.x;
    int tid = blockIdx.x * blockDim.x + threadIdx.x;
    for (int i = tid; i < NIN * H1P; i += stride) {
        int k = i >> 7, h = i & 127;
        g_W1p[i] = (h < H1) ? W1[k * H1 + h] : 0.0f;
    }
    for (int i = tid; i < NIN * BATCH; i += stride) {
        int k = i >> 12, r = i & 4095;
        g_xT[i] = x[r * NIN + k];
    }
    if (tid < NSTEP) {
        unsigned o0, o1;
        tf2x32(0u, 42u, 0u, (unsigned)tid, o0, o1);
        g_keys[tid] = make_uint2(o0, o1);
    }
}

// ---------------- the persistent kernel: all 100 steps in one launch ----------------
__global__ void __launch_bounds__(512, 1)
persist_k(const float* __restrict__ b1,
          const float* __restrict__ W2,
          const float* __restrict__ b2,
          float* __restrict__ out)
{
    extern __shared__ float dyn[];
    float* sh_ws = dyn + OFF_WS;
    unsigned long long* sh_xi = (unsigned long long*)(dyn + OFF_XI);
    float* sh_out = dyn + OFF_OUT;            // [2][RT*128]
    float* w2t    = dyn + OFF_W2T;            // [h2*101 + k]
    float* b2s    = dyn + OFF_B2;
    uint2* skeys  = (uint2*)(dyn + OFF_KEYS);
    float* smacc  = dyn + OFF_ACC;            // [RT*10]

    const int tid = threadIdx.x;
    const int r0  = blockIdx.x * RT;

    // ---- setup ----
    for (int i = tid; i < 2 * RT * H1P; i += 512) sh_out[i] = 0.0f;
    for (int i = tid; i < H1 * H2; i += 512) {
        int k = i / 10, h2 = i - 10 * k;
        w2t[h2 * 101 + k] = W2[i];
    }
    if (tid < H2) b2s[tid] = b2[tid];
    if (tid < NSTEP) skeys[tid] = g_keys[tid];
    __syncthreads();

    if (tid < 256) {
        // ===================== CONSUMERS: 8 warps, 4 rows x 128 h each =====================
        const int lane  = tid & 31;
        const int wrow0 = (tid >> 5) * 4;

        unsigned long long acc2[4][2];
        #pragma unroll
        for (int a = 0; a < 4; ++a) { acc2[a][0] = 0ull; acc2[a][1] = 0ull; }
        float4 in1[4];
        #pragma unroll
        for (int a = 0; a < 4; ++a) in1[a] = make_float4(0.f, 0.f, 0.f, 0.f);
        float4 bias = make_float4(0.f, 0.f, 0.f, 0.f);
        if (lane < 25) bias = *(const float4*)&b1[lane * 4];

        for (int t = 0; t < NSTEP; ++t) {
            for (int c = 0; c < NCHUNK; ++c) {
                __syncthreads();                       // chunk c staged
                const float* ws = sh_ws + (c & 1) * WS_ELE;
                const unsigned long long* xs = sh_xi + (c & 1) * XI_ELE;
                #pragma unroll 7
                for (int k = 0; k < KT; ++k) {
                    const ulonglong2* ap = (const ulonglong2*)(xs + k * RT + wrow0);
                    ulonglong2 aA = ap[0];             // rows 0,1 (dup'd)
                    ulonglong2 aB = ap[1];             // rows 2,3
                    ulonglong2 bv = *(const ulonglong2*)&ws[k * H1P + lane * 4];
                    ffma2(acc2[0][0], aA.x, bv.x); ffma2(acc2[0][1], aA.x, bv.y);
                    ffma2(acc2[1][0], aA.y, bv.x); ffma2(acc2[1][1], aA.y, bv.y);
                    ffma2(acc2[2][0], aB.x, bv.x); ffma2(acc2[2][1], aB.x, bv.y);
                    ffma2(acc2[3][0], aB.y, bv.x); ffma2(acc2[3][1], aB.y, bv.y);
                }
            }
            // ---- LIF: write outer(t) to smem buf[t&1] ----
            float* ob = sh_out + (t & 1) * (RT * H1P);
            #pragma unroll
            for (int rr = 0; rr < 4; ++rr) {
                float e0, e1, e2, e3;
                unpack2(acc2[rr][0], e0, e1);
                unpack2(acc2[rr][1], e2, e3);
                e0 += bias.x; e1 += bias.y; e2 += bias.z; e3 += bias.w;
                float n0 = fmaf(in1[rr].x, 0.9f, e0);
                float n1 = fmaf(in1[rr].y, 0.9f, e1);
                float n2 = fmaf(in1[rr].z, 0.9f, e2);
                float n3 = fmaf(in1[rr].w, 0.9f, e3);
                float o0 = fmaxf(n0 - 1.0f, 0.0f);
                float o1 = fmaxf(n1 - 1.0f, 0.0f);
                float o2 = fmaxf(n2 - 1.0f, 0.0f);
                float o3 = fmaxf(n3 - 1.0f, 0.0f);
                *(float4*)&ob[(wrow0 + rr) * H1P + lane * 4] = make_float4(o0, o1, o2, o3);
                if (o0 > 0.0f) n0 = -0.5f * n0;
                if (o1 > 0.0f) n1 = -0.5f * n1;
                if (o2 > 0.0f) n2 = -0.5f * n2;
                if (o3 > 0.0f) n3 = -0.5f * n3;
                in1[rr] = make_float4(n0, n1, n2, n3);
                acc2[rr][0] = 0ull; acc2[rr][1] = 0ull;
            }
            __syncthreads();                           // step boundary
        }
    } else {
        // ===================== PRODUCERS: 8 warps, RNG + staging + layer2 =====================
        const int ptid = tid - 256;                    // 0..255
        const int lane = tid & 31;
        const int pw   = ptid >> 5;                    // 0..7 -> rows pw*4..pw*4+3

        float in2[4]  = {0.f, 0.f, 0.f, 0.f};
        float l2a[4]  = {0.f, 0.f, 0.f, 0.f};

        // stage chunk (tt, cc) into buf cc&1
        auto do_stage = [&](int tt, int cc) {
            const int buf = cc & 1;
            const int kc  = cc * KT;
            const uint2 key = skeys[tt];
            const float4* wsrc = (const float4*)(g_W1p + cc * WS_ELE);
            float4* wdst = (float4*)(sh_ws + buf * WS_ELE);
            #pragma unroll
            for (int i = 0; i < 7; ++i) wdst[ptid + i * 256] = wsrc[ptid + i * 256];
            unsigned long long* xdst = sh_xi + buf * XI_ELE;
            #pragma unroll
            for (int i = 0; i < 7; ++i) {
                int idx = i * 256 + ptid;
                int k = idx >> 5, row = idx & 31;
                float xv = g_xT[(kc + k) * BATCH + r0 + row];
                unsigned j = (unsigned)((r0 + row) * NIN + kc + k);
                xdst[idx] = dup2(tf_uniform(key.x, key.y, j) * xv);
            }
        };

        do_stage(0, 0);                                // prologue

        for (int t = 0; t < NSTEP; ++t) {
            for (int c = 0; c < NCHUNK; ++c) {
                __syncthreads();                       // consumers start chunk c
                int nt = t, nc = c + 1;
                if (nc == NCHUNK) { nt = t + 1; nc = 0; }
                if (nt < NSTEP) do_stage(nt, nc);
            }
            // ---- layer2(t): uses outer(t-1) = buf[(t+1)&1]; zeros at t=0 ----
            if (lane < H2) {
                const float* po = sh_out + ((t + 1) & 1) * (RT * H1P);
                const float* wr = w2t + lane * 101;
                #pragma unroll
                for (int rr = 0; rr < 4; ++rr) {
                    const float* pr = po + (pw * 4 + rr) * H1P;
                    float s = b2s[lane];
                    #pragma unroll 25
                    for (int k = 0; k < H1; k += 4) {
                        float4 p = *(const float4*)&pr[k];
                        s = fmaf(p.x, wr[k + 0], s);
                        s = fmaf(p.y, wr[k + 1], s);
                        s = fmaf(p.z, wr[k + 2], s);
                        s = fmaf(p.w, wr[k + 3], s);
                    }
                    float pi = in2[rr];
                    if (t >= TBEGIN) l2a[rr] += pi;    // collect DELAYED state
                    float ni = fmaf(pi, 0.9f, s);
                    if (ni - 1.0f > 0.0f) ni = -0.5f * ni;
                    in2[rr] = ni;
                }
            }
            __syncthreads();                           // step boundary
        }

        // dump layer2 accumulators
        if (lane < H2) {
            #pragma unroll
            for (int rr = 0; rr < 4; ++rr)
                smacc[(pw * 4 + rr) * H2 + lane] = l2a[rr];
        }
    }

    // ===================== epilogue: fused log_softmax =====================
    __syncthreads();
    for (int i = tid; i < RT * H2; i += 512) {
        int r = i / 10, c10 = i - 10 * r;
        const float* a = smacc + r * H2;
        float m = a[0];
        #pragma unroll
        for (int j = 1; j < H2; ++j) m = fmaxf(m, a[j]);
        float ssum = 0.0f;
        #pragma unroll
        for (int j = 0; j < H2; ++j) ssum += expf(a[j] - m);
        out[(r0 + r) * H2 + c10] = a[c10] - m - logf(ssum);
    }
}

extern "C" void kernel_launch(void* const* d_in, const int* in_sizes, int n_in,
                              void* d_out, int out_size) {
    const float* x  = (const float*)d_in[0];
    const float* W1 = (const float*)d_in[1];
    const float* b1 = (const float*)d_in[2];
    const float* W2 = (const float*)d_in[3];
    const float* b2 = (const float*)d_in[4];
    float* out = (float*)d_out;

    cudaFuncSetAttribute(persist_k, cudaFuncAttributeMaxDynamicSharedMemorySize, DYN_SMEM);

    init_k<<<1024, 256>>>(W1, x);
    persist_k<<<NCTAS, 512, DYN_SMEM>>>(b1, W2, b2, out);

    (void)in_sizes; (void)n_in; (void)out_size;
}

// round 11
// speedup vs baseline: 1.8267x; 1.0724x over previous
#include <cuda_runtime.h>
#include <cstdint>

#define BATCH  4096
#define NIN    784
#define H1     100
#define H1P    128
#define H2     10
#define NSTEP  100
#define TBEGIN 20
#define KT     56
#define NCHUNK 14
#define KHALF  28                  // KT/2, per consumer half-warp
#define RT     32
#define NCTAS  128                 // 4096 / 32
#define WS_ELE (KT * H1P)          // 7168
#define XI_ELE (KT * RT)           // 1792

// smem layout (float offsets)
#define OFF_WS    0                // [2][7168]
#define OFF_XI    14336            // [2][1792] ull (7168 fl)
#define OFF_OUT   21504            // [2][4096]
#define OFF_IN1   29696            // [4096]
#define OFF_RED   33792            // 2048 ull (4096 fl): 4 pairs x 512 ull
#define OFF_W2T   37888            // [1012]
#define OFF_B2    38900            // [12]
#define OFF_KEYS  38912            // [100] uint2 (200 fl)
#define OFF_ACC   39112            // [320]
#define DYN_SMEM  (39432 * 4)      // 157728 B

// ---------------- device globals ----------------
__device__ float g_W1p[NIN * H1P];
__device__ float g_xT[NIN * BATCH];
__device__ uint2 g_keys[NSTEP];

// ---------------- packed fp32x2 ----------------
__device__ __forceinline__ void ffma2(unsigned long long &a,
                                      unsigned long long xv,
                                      unsigned long long wv) {
    asm("fma.rn.f32x2 %0, %1, %2, %0;" : "+l"(a) : "l"(xv), "l"(wv));
}
__device__ __forceinline__ void fadd2(unsigned long long &a, unsigned long long b) {
    asm("add.rn.f32x2 %0, %0, %1;" : "+l"(a) : "l"(b));
}
__device__ __forceinline__ void unpack2(unsigned long long a, float &lo, float &hi) {
    asm("mov.b64 {%0,%1}, %2;" : "=f"(lo), "=f"(hi) : "l"(a));
}
__device__ __forceinline__ unsigned long long dup2(float v) {
    unsigned long long d;
    asm("mov.b64 %0, {%1,%1};" : "=l"(d) : "f"(v));
    return d;
}

// ---------------- threefry2x32 (JAX-exact) ----------------
__device__ __forceinline__ void tf2x32(unsigned k0, unsigned k1,
                                       unsigned x0, unsigned x1,
                                       unsigned &o0, unsigned &o1) {
    unsigned ks2 = k0 ^ k1 ^ 0x1BD11BDAu;
    x0 += k0; x1 += k1;
#define TFR(r) { x0 += x1; x1 = __funnelshift_l(x1, x1, (r)); x1 ^= x0; }
    TFR(13) TFR(15) TFR(26) TFR(6);  x0 += k1;  x1 += ks2 + 1u;
    TFR(17) TFR(29) TFR(16) TFR(24); x0 += ks2; x1 += k0 + 2u;
    TFR(13) TFR(15) TFR(26) TFR(6);  x0 += k0;  x1 += k1 + 3u;
    TFR(17) TFR(29) TFR(16) TFR(24); x0 += k1;  x1 += ks2 + 4u;
    TFR(13) TFR(15) TFR(26) TFR(6);  x0 += ks2; x1 += k0 + 5u;
#undef TFR
    o0 = x0; o1 = x1;
}
__device__ __forceinline__ float tf_uniform(unsigned k0, unsigned k1, unsigned idx) {
    unsigned o0, o1;
    tf2x32(k0, k1, 0u, idx, o0, o1);
    unsigned bits = o0 ^ o1;
    return __uint_as_float((bits >> 9) | 0x3f800000u) - 1.0f;
}

// ---------------- init ----------------
__global__ void init_k(const float* __restrict__ W1, const float* __restrict__ x) {
    int stride = gridDim.x * blockDim.x;
    int tid = blockIdx.x * blockDim.x + threadIdx.x;
    for (int i = tid; i < NIN * H1P; i += stride) {
        int k = i >> 7, h = i & 127;
        g_W1p[i] = (h < H1) ? W1[k * H1 + h] : 0.0f;
    }
    for (int i = tid; i < NIN * BATCH; i += stride) {
        int k = i >> 12, r = i & 4095;
        g_xT[i] = x[r * NIN + k];
    }
    if (tid < NSTEP) {
        unsigned o0, o1;
        tf2x32(0u, 42u, 0u, (unsigned)tid, o0, o1);
        g_keys[tid] = make_uint2(o0, o1);
    }
}

// ---------------- persistent kernel ----------------
__global__ void __launch_bounds__(512, 1)
persist_k(const float* __restrict__ b1,
          const float* __restrict__ W2,
          const float* __restrict__ b2,
          float* __restrict__ out)
{
    extern __shared__ float dyn[];
    float* sh_ws = dyn + OFF_WS;
    unsigned long long* sh_xi  = (unsigned long long*)(dyn + OFF_XI);
    float* sh_out = dyn + OFF_OUT;
    float* sh_in1 = dyn + OFF_IN1;
    unsigned long long* sh_red = (unsigned long long*)(dyn + OFF_RED);
    float* w2t    = dyn + OFF_W2T;
    float* b2s    = dyn + OFF_B2;
    uint2* skeys  = (uint2*)(dyn + OFF_KEYS);
    float* smacc  = dyn + OFF_ACC;

    const int tid = threadIdx.x;
    const int r0  = blockIdx.x * RT;

    // ---- setup ----
    for (int i = tid; i < 2 * RT * H1P; i += 512) sh_out[i] = 0.0f;
    for (int i = tid; i < RT * H1P; i += 512) sh_in1[i] = 0.0f;
    for (int i = tid; i < H1 * H2; i += 512) {
        int k = i / 10, h2 = i - 10 * k;
        w2t[h2 * 101 + k] = W2[i];
    }
    if (tid < H2) b2s[tid] = b2[tid];
    if (tid < NSTEP) skeys[tid] = g_keys[tid];
    __syncthreads();

    if (tid < 256) {
        // ============ CONSUMERS: 4 warp-pairs, each pair: 8 rows x 128 h, k split ============
        const int lane  = tid & 31;
        const int w     = tid >> 5;
        const int pair  = w >> 1;
        const int half  = w & 1;
        const int prow0 = pair * 8;
        const int kbase = half * KHALF;

        unsigned long long acc2[8][2];
        #pragma unroll
        for (int a = 0; a < 8; ++a) { acc2[a][0] = 0ull; acc2[a][1] = 0ull; }
        float4 bias = make_float4(0.f, 0.f, 0.f, 0.f);
        if (lane < 25) bias = *(const float4*)&b1[lane * 4];

        unsigned long long* red = sh_red + pair * 512;

        for (int t = 0; t < NSTEP; ++t) {
            for (int c = 0; c < NCHUNK; ++c) {
                __syncthreads();                       // chunk c staged
                const float* ws = sh_ws + (c & 1) * WS_ELE;
                const unsigned long long* xs = sh_xi + (c & 1) * XI_ELE;
                #pragma unroll 7
                for (int k = 0; k < KHALF; ++k) {
                    const int kk = kbase + k;
                    const ulonglong2* ap = (const ulonglong2*)(xs + kk * RT + prow0);
                    ulonglong2 aA = ap[0];             // rows 0,1
                    ulonglong2 aB = ap[1];             // rows 2,3
                    ulonglong2 aC = ap[2];             // rows 4,5
                    ulonglong2 aD = ap[3];             // rows 6,7
                    ulonglong2 bv = *(const ulonglong2*)&ws[kk * H1P + lane * 4];
                    ffma2(acc2[0][0], aA.x, bv.x); ffma2(acc2[0][1], aA.x, bv.y);
                    ffma2(acc2[1][0], aA.y, bv.x); ffma2(acc2[1][1], aA.y, bv.y);
                    ffma2(acc2[2][0], aB.x, bv.x); ffma2(acc2[2][1], aB.x, bv.y);
                    ffma2(acc2[3][0], aB.y, bv.x); ffma2(acc2[3][1], aB.y, bv.y);
                    ffma2(acc2[4][0], aC.x, bv.x); ffma2(acc2[4][1], aC.x, bv.y);
                    ffma2(acc2[5][0], aC.y, bv.x); ffma2(acc2[5][1], aC.y, bv.y);
                    ffma2(acc2[6][0], aD.x, bv.x); ffma2(acc2[6][1], aD.x, bv.y);
                    ffma2(acc2[7][0], aD.y, bv.x); ffma2(acc2[7][1], aD.y, bv.y);
                }
            }

            // ---- pair reduction: half 1 -> smem, half 0 merges ----
            if (half) {
                #pragma unroll
                for (int i = 0; i < 8; ++i) {
                    red[(i * 2 + 0) * 32 + lane] = acc2[i][0];
                    red[(i * 2 + 1) * 32 + lane] = acc2[i][1];
                }
            }
            asm volatile("bar.sync %0, %1;" :: "r"(pair + 1), "r"(64) : "memory");
            if (!half) {
                #pragma unroll
                for (int i = 0; i < 8; ++i) {
                    fadd2(acc2[i][0], red[(i * 2 + 0) * 32 + lane]);
                    fadd2(acc2[i][1], red[(i * 2 + 1) * 32 + lane]);
                }
                // ---- LIF for 8 rows ----
                float* ob = sh_out + (t & 1) * (RT * H1P);
                #pragma unroll
                for (int rr = 0; rr < 8; ++rr) {
                    int row = prow0 + rr;
                    float e0, e1, e2, e3;
                    unpack2(acc2[rr][0], e0, e1);
                    unpack2(acc2[rr][1], e2, e3);
                    e0 += bias.x; e1 += bias.y; e2 += bias.z; e3 += bias.w;
                    float4 piv = *(const float4*)&sh_in1[row * H1P + lane * 4];
                    float n0 = fmaf(piv.x, 0.9f, e0);
                    float n1 = fmaf(piv.y, 0.9f, e1);
                    float n2 = fmaf(piv.z, 0.9f, e2);
                    float n3 = fmaf(piv.w, 0.9f, e3);
                    float o0 = fmaxf(n0 - 1.0f, 0.0f);
                    float o1 = fmaxf(n1 - 1.0f, 0.0f);
                    float o2 = fmaxf(n2 - 1.0f, 0.0f);
                    float o3 = fmaxf(n3 - 1.0f, 0.0f);
                    *(float4*)&ob[row * H1P + lane * 4] = make_float4(o0, o1, o2, o3);
                    if (o0 > 0.0f) n0 = -0.5f * n0;
                    if (o1 > 0.0f) n1 = -0.5f * n1;
                    if (o2 > 0.0f) n2 = -0.5f * n2;
                    if (o3 > 0.0f) n3 = -0.5f * n3;
                    *(float4*)&sh_in1[row * H1P + lane * 4] = make_float4(n0, n1, n2, n3);
                }
            }
            #pragma unroll
            for (int a = 0; a < 8; ++a) { acc2[a][0] = 0ull; acc2[a][1] = 0ull; }
            __syncthreads();                           // step boundary
        }
    } else {
        // ============ PRODUCERS: 8 warps, RNG + staging + layer2 ============
        const int ptid = tid - 256;
        const int lane = tid & 31;
        const int pw   = ptid >> 5;

        float in2[4] = {0.f, 0.f, 0.f, 0.f};
        float l2a[4] = {0.f, 0.f, 0.f, 0.f};

        auto do_stage = [&](int tt, int cc) {
            const int buf = cc & 1;
            const int kc  = cc * KT;
            const uint2 key = skeys[tt];
            const float4* wsrc = (const float4*)(g_W1p + cc * WS_ELE);
            float4* wdst = (float4*)(sh_ws + buf * WS_ELE);
            #pragma unroll
            for (int i = 0; i < 7; ++i) wdst[ptid + i * 256] = wsrc[ptid + i * 256];
            unsigned long long* xdst = sh_xi + buf * XI_ELE;
            #pragma unroll
            for (int i = 0; i < 7; ++i) {
                int idx = i * 256 + ptid;
                int k = idx >> 5, row = idx & 31;
                float xv = g_xT[(kc + k) * BATCH + r0 + row];
                unsigned j = (unsigned)((r0 + row) * NIN + kc + k);
                xdst[idx] = dup2(tf_uniform(key.x, key.y, j) * xv);
            }
        };

        do_stage(0, 0);

        for (int t = 0; t < NSTEP; ++t) {
            for (int c = 0; c < NCHUNK; ++c) {
                __syncthreads();
                int nt = t, nc = c + 1;
                if (nc == NCHUNK) { nt = t + 1; nc = 0; }
                if (nt < NSTEP) do_stage(nt, nc);
            }
            // layer2(t): reads outer(t-1) = buf[(t+1)&1]
            if (lane < H2) {
                const float* po = sh_out + ((t + 1) & 1) * (RT * H1P);
                const float* wr = w2t + lane * 101;
                #pragma unroll
                for (int rr = 0; rr < 4; ++rr) {
                    const float* pr = po + (pw * 4 + rr) * H1P;
                    float s = b2s[lane];
                    #pragma unroll 25
                    for (int k = 0; k < H1; k += 4) {
                        float4 p = *(const float4*)&pr[k];
                        s = fmaf(p.x, wr[k + 0], s);
                        s = fmaf(p.y, wr[k + 1], s);
                        s = fmaf(p.z, wr[k + 2], s);
                        s = fmaf(p.w, wr[k + 3], s);
                    }
                    float pi = in2[rr];
                    if (t >= TBEGIN) l2a[rr] += pi;
                    float ni = fmaf(pi, 0.9f, s);
                    if (ni - 1.0f > 0.0f) ni = -0.5f * ni;
                    in2[rr] = ni;
                }
            }
            __syncthreads();                           // step boundary
        }

        if (lane < H2) {
            #pragma unroll
            for (int rr = 0; rr < 4; ++rr)
                smacc[(pw * 4 + rr) * H2 + lane] = l2a[rr];
        }
    }

    // ---- epilogue: fused log_softmax ----
    __syncthreads();
    for (int i = tid; i < RT * H2; i += 512) {
        int r = i / 10, c10 = i - 10 * r;
        const float* a = smacc + r * H2;
        float m = a[0];
        #pragma unroll
        for (int j = 1; j < H2; ++j) m = fmaxf(m, a[j]);
        float ssum = 0.0f;
        #pragma unroll
        for (int j = 0; j < H2; ++j) ssum += expf(a[j] - m);
        out[(r0 + r) * H2 + c10] = a[c10] - m - logf(ssum);
    }
}

extern "C" void kernel_launch(void* const* d_in, const int* in_sizes, int n_in,
                              void* d_out, int out_size) {
    const float* x  = (const float*)d_in[0];
    const float* W1 = (const float*)d_in[1];
    const float* b1 = (const float*)d_in[2];
    const float* W2 = (const float*)d_in[3];
    const float* b2 = (const float*)d_in[4];
    float* out = (float*)d_out;

    cudaFuncSetAttribute(persist_k, cudaFuncAttributeMaxDynamicSharedMemorySize, DYN_SMEM);

    init_k<<<1024, 256>>>(W1, x);
    persist_k<<<NCTAS, 512, DYN_SMEM>>>(b1, W2, b2, out);

    (void)in_sizes; (void)n_in; (void)out_size;
}

// round 13
// speedup vs baseline: 1.8811x; 1.0298x over previous
#include <cuda_runtime.h>
#include <cstdint>

#define BATCH  4096
#define BATCHP 4128                // padded rows in g_xT
#define NIN    784
#define H1     100
#define H1P    128
#define H2     10
#define NSTEP  100
#define TBEGIN 20
#define KT     56
#define NCHUNK 14
#define KHALF  28                  // KT/2 per consumer half
#define RT     28                  // rows per CTA (4 pairs x 7 rows)
#define NCTAS  147                 // ceil(4096/28)
#define NXI    1568                // KT*RT real evals per chunk
#define WS_ELE (KT * H1P)          // 7168 floats
#define XI_SLOT (KT * 32)          // 1792 ull slots per buffer (8-slot pair stride)

// smem layout (float offsets)
#define OFF_WS    0                // [2][7168]
#define OFF_XI    14336            // [2][1792] ull = 14336 fl
#define OFF_OUT   28672            // [2][28*128] = 7168
#define OFF_IN1   35840            // [28*128] = 3584
#define OFF_RED   39424            // 2048 ull = 4096 fl (4 pairs x 512)
#define OFF_W2T   43520            // 1012
#define OFF_B2    44532            // 12
#define OFF_KEYS  44544            // 100 uint2 = 200
#define OFF_ACC   44744            // 280
#define DYN_SMEM  (45024 * 4)      // 180096 B

// ---------------- device globals ----------------
__device__ float g_W1p[NIN * H1P];
__device__ float g_xT[NIN * BATCHP];
__device__ uint2 g_keys[NSTEP];

// ---------------- packed fp32x2 ----------------
__device__ __forceinline__ void ffma2(unsigned long long &a,
                                      unsigned long long xv,
                                      unsigned long long wv) {
    asm("fma.rn.f32x2 %0, %1, %2, %0;" : "+l"(a) : "l"(xv), "l"(wv));
}
__device__ __forceinline__ void fadd2(unsigned long long &a, unsigned long long b) {
    asm("add.rn.f32x2 %0, %0, %1;" : "+l"(a) : "l"(b));
}
__device__ __forceinline__ void unpack2(unsigned long long a, float &lo, float &hi) {
    asm("mov.b64 {%0,%1}, %2;" : "=f"(lo), "=f"(hi) : "l"(a));
}
__device__ __forceinline__ unsigned long long dup2(float v) {
    unsigned long long d;
    asm("mov.b64 %0, {%1,%1};" : "=l"(d) : "f"(v));
    return d;
}

// ---------------- threefry2x32 (JAX-exact) ----------------
__device__ __forceinline__ void tf2x32(unsigned k0, unsigned k1,
                                       unsigned x0, unsigned x1,
                                       unsigned &o0, unsigned &o1) {
    unsigned ks2 = k0 ^ k1 ^ 0x1BD11BDAu;
    x0 += k0; x1 += k1;
#define TFR(r) { x0 += x1; x1 = __funnelshift_l(x1, x1, (r)); x1 ^= x0; }
    TFR(13) TFR(15) TFR(26) TFR(6);  x0 += k1;  x1 += ks2 + 1u;
    TFR(17) TFR(29) TFR(16) TFR(24); x0 += ks2; x1 += k0 + 2u;
    TFR(13) TFR(15) TFR(26) TFR(6);  x0 += k0;  x1 += k1 + 3u;
    TFR(17) TFR(29) TFR(16) TFR(24); x0 += k1;  x1 += ks2 + 4u;
    TFR(13) TFR(15) TFR(26) TFR(6);  x0 += ks2; x1 += k0 + 5u;
#undef TFR
    o0 = x0; o1 = x1;
}
__device__ __forceinline__ float tf_uniform(unsigned k0, unsigned k1, unsigned idx) {
    unsigned o0, o1;
    tf2x32(k0, k1, 0u, idx, o0, o1);
    unsigned bits = o0 ^ o1;
    return __uint_as_float((bits >> 9) | 0x3f800000u) - 1.0f;
}

// ---------------- init ----------------
__global__ void init_k(const float* __restrict__ W1, const float* __restrict__ x) {
    int stride = gridDim.x * blockDim.x;
    int tid = blockIdx.x * blockDim.x + threadIdx.x;
    for (int i = tid; i < NIN * H1P; i += stride) {
        int k = i >> 7, h = i & 127;
        g_W1p[i] = (h < H1) ? W1[k * H1 + h] : 0.0f;
    }
    for (int i = tid; i < NIN * BATCHP; i += stride) {
        int k = i / BATCHP, r = i - k * BATCHP;
        g_xT[i] = (r < BATCH) ? x[r * NIN + k] : 0.0f;
    }
    if (tid < NSTEP) {
        unsigned o0, o1;
        tf2x32(0u, 42u, 0u, (unsigned)tid, o0, o1);
        g_keys[tid] = make_uint2(o0, o1);
    }
}

// ---------------- persistent kernel ----------------
__global__ void __launch_bounds__(512, 1)
persist_k(const float* __restrict__ b1,
          const float* __restrict__ W2,
          const float* __restrict__ b2,
          float* __restrict__ out)
{
    extern __shared__ float dyn[];
    float* sh_ws = dyn + OFF_WS;
    unsigned long long* sh_xi  = (unsigned long long*)(dyn + OFF_XI);
    float* sh_out = dyn + OFF_OUT;            // [2][RT*128]
    float* sh_in1 = dyn + OFF_IN1;            // [RT*128]
    unsigned long long* sh_red = (unsigned long long*)(dyn + OFF_RED);
    float* w2t    = dyn + OFF_W2T;
    float* b2s    = dyn + OFF_B2;
    uint2* skeys  = (uint2*)(dyn + OFF_KEYS);
    float* smacc  = dyn + OFF_ACC;            // [RT*10]

    const int tid = threadIdx.x;
    const int r0  = blockIdx.x * RT;

    // ---- setup ----
    for (int i = tid; i < 2 * RT * H1P; i += 512) sh_out[i] = 0.0f;
    for (int i = tid; i < RT * H1P; i += 512) sh_in1[i] = 0.0f;
    for (int i = tid; i < H1 * H2; i += 512) {
        int k = i / 10, h2 = i - 10 * k;
        w2t[h2 * 101 + k] = W2[i];
    }
    if (tid < H2) b2s[tid] = b2[tid];
    if (tid < NSTEP) skeys[tid] = g_keys[tid];
    __syncthreads();

    if (tid < 256) {
        // ===== CONSUMERS: 4 warp-pairs, each pair 7 rows x 128 h, k split =====
        const int lane  = tid & 31;
        const int w     = tid >> 5;
        const int pair  = w >> 1;
        const int half  = w & 1;
        const int slot0 = pair * 8;            // xi slot base (8-slot stride)
        const int row0  = pair * 7;            // tight row base
        const int kbase = half * KHALF;

        unsigned long long acc2[7][2];
        #pragma unroll
        for (int a = 0; a < 7; ++a) { acc2[a][0] = 0ull; acc2[a][1] = 0ull; }
        float4 bias = make_float4(0.f, 0.f, 0.f, 0.f);
        if (lane < 25) bias = *(const float4*)&b1[lane * 4];

        unsigned long long* red = sh_red + pair * 512;

        for (int t = 0; t < NSTEP; ++t) {
            for (int c = 0; c < NCHUNK; ++c) {
                __syncthreads();                       // chunk c staged
                const float* ws = sh_ws + (c & 1) * WS_ELE;
                const unsigned long long* xs = sh_xi + (c & 1) * XI_SLOT;
                #pragma unroll 7
                for (int k = 0; k < KHALF; ++k) {
                    const int kk = kbase + k;
                    const ulonglong2* ap = (const ulonglong2*)(xs + kk * 32 + slot0);
                    ulonglong2 aA = ap[0];             // rows 0,1
                    ulonglong2 aB = ap[1];             // rows 2,3
                    ulonglong2 aC = ap[2];             // rows 4,5
                    ulonglong2 aD = ap[3];             // rows 6,(pad)
                    ulonglong2 bv = *(const ulonglong2*)&ws[kk * H1P + lane * 4];
                    ffma2(acc2[0][0], aA.x, bv.x); ffma2(acc2[0][1], aA.x, bv.y);
                    ffma2(acc2[1][0], aA.y, bv.x); ffma2(acc2[1][1], aA.y, bv.y);
                    ffma2(acc2[2][0], aB.x, bv.x); ffma2(acc2[2][1], aB.x, bv.y);
                    ffma2(acc2[3][0], aB.y, bv.x); ffma2(acc2[3][1], aB.y, bv.y);
                    ffma2(acc2[4][0], aC.x, bv.x); ffma2(acc2[4][1], aC.x, bv.y);
                    ffma2(acc2[5][0], aC.y, bv.x); ffma2(acc2[5][1], aC.y, bv.y);
                    ffma2(acc2[6][0], aD.x, bv.x); ffma2(acc2[6][1], aD.x, bv.y);
                }
            }

            // ---- pair reduction ----
            if (half) {
                #pragma unroll
                for (int i = 0; i < 7; ++i) {
                    red[(i * 2 + 0) * 32 + lane] = acc2[i][0];
                    red[(i * 2 + 1) * 32 + lane] = acc2[i][1];
                }
            }
            asm volatile("bar.sync %0, %1;" :: "r"(pair + 1), "r"(64) : "memory");
            if (!half) {
                #pragma unroll
                for (int i = 0; i < 7; ++i) {
                    fadd2(acc2[i][0], red[(i * 2 + 0) * 32 + lane]);
                    fadd2(acc2[i][1], red[(i * 2 + 1) * 32 + lane]);
                }
                float* ob = sh_out + (t & 1) * (RT * H1P);
                #pragma unroll
                for (int rr = 0; rr < 7; ++rr) {
                    int row = row0 + rr;
                    float e0, e1, e2, e3;
                    unpack2(acc2[rr][0], e0, e1);
                    unpack2(acc2[rr][1], e2, e3);
                    e0 += bias.x; e1 += bias.y; e2 += bias.z; e3 += bias.w;
                    float4 piv = *(const float4*)&sh_in1[row * H1P + lane * 4];
                    float n0 = fmaf(piv.x, 0.9f, e0);
                    float n1 = fmaf(piv.y, 0.9f, e1);
                    float n2 = fmaf(piv.z, 0.9f, e2);
                    float n3 = fmaf(piv.w, 0.9f, e3);
                    float o0 = fmaxf(n0 - 1.0f, 0.0f);
                    float o1 = fmaxf(n1 - 1.0f, 0.0f);
                    float o2 = fmaxf(n2 - 1.0f, 0.0f);
                    float o3 = fmaxf(n3 - 1.0f, 0.0f);
                    *(float4*)&ob[row * H1P + lane * 4] = make_float4(o0, o1, o2, o3);
                    if (o0 > 0.0f) n0 = -0.5f * n0;
                    if (o1 > 0.0f) n1 = -0.5f * n1;
                    if (o2 > 0.0f) n2 = -0.5f * n2;
                    if (o3 > 0.0f) n3 = -0.5f * n3;
                    *(float4*)&sh_in1[row * H1P + lane * 4] = make_float4(n0, n1, n2, n3);
                }
            }
            #pragma unroll
            for (int a = 0; a < 7; ++a) { acc2[a][0] = 0ull; acc2[a][1] = 0ull; }
        }
    } else {
        // ===== PRODUCERS: 8 warps, RNG + staging + layer2 =====
        const int ptid = tid - 256;
        const int lane = tid & 31;
        const int pw   = ptid >> 5;            // 0..7; pw<7 handles 4 rows

        float in2[4] = {0.f, 0.f, 0.f, 0.f};
        float l2a[4] = {0.f, 0.f, 0.f, 0.f};

        auto do_stage = [&](int tt, int cc) {
            const int buf = cc & 1;
            const int kc  = cc * KT;
            const uint2 key = skeys[tt];
            const float4* wsrc = (const float4*)(g_W1p + cc * WS_ELE);
            float4* wdst = (float4*)(sh_ws + buf * WS_ELE);
            #pragma unroll
            for (int i = 0; i < 7; ++i) wdst[ptid + i * 256] = wsrc[ptid + i * 256];
            unsigned long long* xdst = sh_xi + buf * XI_SLOT;
            #pragma unroll
            for (int i = 0; i < 7; ++i) {
                int idx = i * 256 + ptid;
                if (idx < NXI) {
                    int k   = idx / RT;                // 0..55
                    int row = idx - k * RT;            // 0..27
                    int p7  = row / 7;
                    int slot = p7 * 8 + (row - p7 * 7);
                    float xv = g_xT[(kc + k) * BATCHP + r0 + row];
                    unsigned j = (unsigned)((r0 + row) * NIN + kc + k);
                    xdst[k * 32 + slot] = dup2(tf_uniform(key.x, key.y, j) * xv);
                }
            }
        };

        do_stage(0, 0);

        for (int t = 0; t < NSTEP; ++t) {
            for (int c = 0; c < NCHUNK; ++c) {
                __syncthreads();
                int nt = t, nc = c + 1;
                if (nc == NCHUNK) { nt = t + 1; nc = 0; }
                if (nt < NSTEP) do_stage(nt, nc);
            }
            // layer2(t): reads outer(t-1) = buf[(t+1)&1]
            if (lane < H2 && pw < 7) {
                const float* po = sh_out + ((t + 1) & 1) * (RT * H1P);
                const float* wr = w2t + lane * 101;
                #pragma unroll
                for (int rr = 0; rr < 4; ++rr) {
                    const float* pr = po + (pw * 4 + rr) * H1P;
                    float s = b2s[lane];
                    #pragma unroll 25
                    for (int k = 0; k < H1; k += 4) {
                        float4 p = *(const float4*)&pr[k];
                        s = fmaf(p.x, wr[k + 0], s);
                        s = fmaf(p.y, wr[k + 1], s);
                        s = fmaf(p.z, wr[k + 2], s);
                        s = fmaf(p.w, wr[k + 3], s);
                    }
                    float pi = in2[rr];
                    if (t >= TBEGIN) l2a[rr] += pi;
                    float ni = fmaf(pi, 0.9f, s);
                    if (ni - 1.0f > 0.0f) ni = -0.5f * ni;
                    in2[rr] = ni;
                }
            }
        }

        if (lane < H2 && pw < 7) {
            #pragma unroll
            for (int rr = 0; rr < 4; ++rr)
                smacc[(pw * 4 + rr) * H2 + lane] = l2a[rr];
        }
    }

    // ---- epilogue: fused log_softmax ----
    __syncthreads();
    for (int i = tid; i < RT * H2; i += 512) {
        int r = i / 10, c10 = i - 10 * r;
        if (r0 + r < BATCH) {
            const float* a = smacc + r * H2;
            float m = a[0];
            #pragma unroll
            for (int j = 1; j < H2; ++j) m = fmaxf(m, a[j]);
            float ssum = 0.0f;
            #pragma unroll
            for (int j = 0; j < H2; ++j) ssum += expf(a[j] - m);
            out[(r0 + r) * H2 + c10] = a[c10] - m - logf(ssum);
        }
    }
}

extern "C" void kernel_launch(void* const* d_in, const int* in_sizes, int n_in,
                              void* d_out, int out_size) {
    const float* x  = (const float*)d_in[0];
    const float* W1 = (const float*)d_in[1];
    const float* b1 = (const float*)d_in[2];
    const float* W2 = (const float*)d_in[3];
    const float* b2 = (const float*)d_in[4];
    float* out = (float*)d_out;

    cudaFuncSetAttribute(persist_k, cudaFuncAttributeMaxDynamicSharedMemorySize, DYN_SMEM);

    init_k<<<1024, 256>>>(W1, x);
    persist_k<<<NCTAS, 512, DYN_SMEM>>>(b1, W2, b2, out);

    (void)in_sizes; (void)n_in; (void)out_size;
}